// round 12
// baseline (speedup 1.0000x reference)
#include <cuda_runtime.h>
#include <cuda_fp16.h>
#include <cuda_bf16.h>

// GCN: 2-layer graph conv, N=100000, E=1.6M, 128 -> 32 -> 32.
// Round 12: edge-parallel segmented aggregation (perfect load balance) replacing
// dst-parallel gathers; epilogues folded (mid loads relu(agg1+b1); edge_agg2 reds
// straight into d_out pre-initialized to b2).
//   side stream : gemm1 (feat @ W1 -> g_hh fp16, UNSCALED)
//   main stream : zero(degs,agg1,out=b2) -> degrees(int4) -> scanA(+norms)
//                 -> scanB -> scatter(src,dst pairs)
//   join
//   edge_agg1   : agg1[d] +=red (sum_seg h[s]*no[s]) * ni[d]
//   mid         : g_hh2 = (relu(agg1+b1) @ W2) * norm_out      [fp16]
//   edge_agg2   : d_out[d] +=red (sum_seg h2[s]) * ni[d]       (out pre-init b2)

#define MAXN 100000
#define MAXE 1600000
#define SCAN_B 512

__device__ int    g_deg_out[MAXN];
__device__ int    g_deg_in[MAXN];
__device__ float  g_norm_out[MAXN];
__device__ float  g_norm_in[MAXN];
__device__ int    g_offset[MAXN];
__device__ int    g_cursor[MAXN];
__device__ int2   g_csr2[MAXE];        // (src, dst) grouped by dst
__device__ int    g_blocksums[(MAXN + SCAN_B - 1) / SCAN_B];
__device__ uint4  g_hh [MAXN * 4];     // fp16 h rows (unscaled), 64B each
__device__ uint4  g_hh2[MAXN * 4];     // fp16 h2 rows (pre-scaled by norm_out)
__device__ float  g_agg1[MAXN * 32];   // layer-1 aggregate (incl. *norm_in)

// ---- helpers ----
__device__ __forceinline__ void red_add_v4(float* addr, float4 v) {
    asm volatile("red.global.add.v4.f32 [%0], {%1, %2, %3, %4};"
                 :: "l"(addr), "f"(v.x), "f"(v.y), "f"(v.z), "f"(v.w)
                 : "memory");
}
__device__ __forceinline__ uint2 pack_h4(float4 a) {
    __half2 lo = __floats2half2_rn(a.x, a.y);
    __half2 hi = __floats2half2_rn(a.z, a.w);
    uint2 u;
    u.x = *(const unsigned int*)&lo;
    u.y = *(const unsigned int*)&hi;
    return u;
}
__device__ __forceinline__ void acc_h8(float* acc, uint4 u, float s) {
    float2 f0 = __half22float2(*(const __half2*)&u.x);
    float2 f1 = __half22float2(*(const __half2*)&u.y);
    float2 f2 = __half22float2(*(const __half2*)&u.z);
    float2 f3 = __half22float2(*(const __half2*)&u.w);
    acc[0] += f0.x * s; acc[1] += f0.y * s;
    acc[2] += f1.x * s; acc[3] += f1.y * s;
    acc[4] += f2.x * s; acc[5] += f2.y * s;
    acc[6] += f3.x * s; acc[7] += f3.y * s;
}
__device__ __forceinline__ void flush8(float* basep, const float* acc, float m) {
    float4 a = make_float4(acc[0]*m, acc[1]*m, acc[2]*m, acc[3]*m);
    float4 b = make_float4(acc[4]*m, acc[5]*m, acc[6]*m, acc[7]*m);
    red_add_v4(basep, a);
    red_add_v4(basep + 4, b);
}

// ---------------------------------------------------------------- zero + out init
__global__ void zero_kernel(float4* __restrict__ out, const float* __restrict__ b2, int n) {
    int i = blockIdx.x * blockDim.x + threadIdx.x;
    if (i < n) { g_deg_out[i] = 0; g_deg_in[i] = 0; g_cursor[i] = 0; }
    if (i < n * 8) {
        ((float4*)g_agg1)[i] = make_float4(0.f, 0.f, 0.f, 0.f);
        out[i] = __ldg(&((const float4*)b2)[i & 7]);
    }
}

// ---------------------------------------------------------------- degrees (int4)
__global__ void degree_kernel(const int* __restrict__ src,
                              const int* __restrict__ dst, int E) {
    int i = blockIdx.x * blockDim.x + threadIdx.x;
    int base = i * 4;
    if (base + 3 < E) {
        int4 s = *(const int4*)&src[base];
        int4 d = *(const int4*)&dst[base];
        atomicAdd(&g_deg_out[s.x], 1);
        atomicAdd(&g_deg_out[s.y], 1);
        atomicAdd(&g_deg_out[s.z], 1);
        atomicAdd(&g_deg_out[s.w], 1);
        atomicAdd(&g_deg_in[d.x], 1);
        atomicAdd(&g_deg_in[d.y], 1);
        atomicAdd(&g_deg_in[d.z], 1);
        atomicAdd(&g_deg_in[d.w], 1);
    } else {
        for (int e = base; e < E; e++) {
            atomicAdd(&g_deg_out[src[e]], 1);
            atomicAdd(&g_deg_in[dst[e]], 1);
        }
    }
}

// ---------------------------------------------------------------- scanA + norms
__global__ __launch_bounds__(SCAN_B) void scanA_norm_kernel(int n) {
    __shared__ int swarp[16];
    int t = threadIdx.x;
    int i = blockIdx.x * SCAN_B + t;
    int v = 0;
    if (i < n) {
        int din = g_deg_in[i];
        v = din;
        g_norm_in[i]  = rsqrtf(fmaxf((float)din, 1.f));
        g_norm_out[i] = rsqrtf(fmaxf((float)g_deg_out[i], 1.f));
    }
    int lane = t & 31, w = t >> 5;
    int x = v;
    #pragma unroll
    for (int d = 1; d < 32; d <<= 1) {
        int y = __shfl_up_sync(0xffffffffu, x, d);
        if (lane >= d) x += y;
    }
    if (lane == 31) swarp[w] = x;
    __syncthreads();
    if (w == 0 && t < 16) {
        int y = swarp[t];
        #pragma unroll
        for (int d = 1; d < 16; d <<= 1) {
            int z = __shfl_up_sync(0xffffu, y, d);
            if (t >= d) y += z;
        }
        swarp[t] = y;
    }
    __syncthreads();
    int base = (w > 0) ? swarp[w - 1] : 0;
    int incl = x + base;
    if (i < n) g_offset[i] = incl - v;
    if (t == SCAN_B - 1) g_blocksums[blockIdx.x] = incl;
}

// ---------------------------------------------------------------- scanB
__global__ __launch_bounds__(256) void scanB_kernel(int nb) {
    __shared__ int swarp[8];
    int t = threadIdx.x;
    int v = (t < nb) ? g_blocksums[t] : 0;
    int lane = t & 31, w = t >> 5;
    int x = v;
    #pragma unroll
    for (int d = 1; d < 32; d <<= 1) {
        int y = __shfl_up_sync(0xffffffffu, x, d);
        if (lane >= d) x += y;
    }
    if (lane == 31) swarp[w] = x;
    __syncthreads();
    if (w == 0 && t < 8) {
        int y = swarp[t];
        #pragma unroll
        for (int d = 1; d < 8; d <<= 1) {
            int z = __shfl_up_sync(0xffu, y, d);
            if (t >= d) y += z;
        }
        swarp[t] = y;
    }
    __syncthreads();
    int base = (w > 0) ? swarp[w - 1] : 0;
    if (t < nb) g_blocksums[t] = x + base - v;
}

// ---------------------------------------------------------------- scatter (src,dst) pairs
__global__ void scatter_kernel(const int* __restrict__ src,
                               const int* __restrict__ dst, int E) {
    int e = blockIdx.x * blockDim.x + threadIdx.x;
    if (e < E) {
        int d = dst[e];
        int p = atomicAdd(&g_cursor[d], 1);
        g_csr2[g_offset[d] + g_blocksums[d >> 9] + p] = make_int2(src[e], d);
    }
}

// ---------------------------------------------------------------- GEMM1 (feat @ W1 -> fp16, UNSCALED)
__global__ __launch_bounds__(256) void gemm1_kernel(const float* __restrict__ feat,
                                                    const float* __restrict__ W1, int n) {
    extern __shared__ float4 dyn[];
    float4* sW = dyn;            // [k=128][cg=8]
    float4* sF = dyn + 1024;     // [row=128][k4=32] swizzled
    int t = threadIdx.x;

    for (int i = t; i < 1024; i += 256) sW[i] = ((const float4*)W1)[i];
    int row0 = blockIdx.x * 128;
    #pragma unroll
    for (int j = 0; j < 16; j++) {
        int i = t + j * 256;
        int r = i >> 5, k4 = i & 31;
        int gr = row0 + r;
        float4 v = make_float4(0.f, 0.f, 0.f, 0.f);
        if (gr < n) v = ((const float4*)feat)[gr * 32 + k4];
        sF[r * 32 + (k4 ^ (r & 7))] = v;
    }
    __syncthreads();

    int rt = t >> 3, cg = t & 7;
    int sw = rt & 7;
    const float4* fp0 = &sF[(rt +  0) * 32];
    const float4* fp1 = &sF[(rt + 32) * 32];
    const float4* fp2 = &sF[(rt + 64) * 32];
    const float4* fp3 = &sF[(rt + 96) * 32];

    float4 a0 = make_float4(0.f,0.f,0.f,0.f), a1 = a0, a2 = a0, a3 = a0;

    #pragma unroll 4
    for (int k4 = 0; k4 < 32; k4++) {
        float4 f0 = fp0[k4 ^ sw];
        float4 f1 = fp1[k4 ^ sw];
        float4 f2 = fp2[k4 ^ sw];
        float4 f3 = fp3[k4 ^ sw];
        #pragma unroll
        for (int i = 0; i < 4; i++) {
            float4 w = sW[(k4 * 4 + i) * 8 + cg];
            float c0 = (i == 0) ? f0.x : (i == 1) ? f0.y : (i == 2) ? f0.z : f0.w;
            float c1 = (i == 0) ? f1.x : (i == 1) ? f1.y : (i == 2) ? f1.z : f1.w;
            float c2 = (i == 0) ? f2.x : (i == 1) ? f2.y : (i == 2) ? f2.z : f2.w;
            float c3 = (i == 0) ? f3.x : (i == 1) ? f3.y : (i == 2) ? f3.z : f3.w;
            a0.x += c0*w.x; a0.y += c0*w.y; a0.z += c0*w.z; a0.w += c0*w.w;
            a1.x += c1*w.x; a1.y += c1*w.y; a1.z += c1*w.z; a1.w += c1*w.w;
            a2.x += c2*w.x; a2.y += c2*w.y; a2.z += c2*w.z; a2.w += c2*w.w;
            a3.x += c3*w.x; a3.y += c3*w.y; a3.z += c3*w.z; a3.w += c3*w.w;
        }
    }

    uint2* hh = (uint2*)g_hh;
    int gr;
    gr = row0 + rt;      if (gr < n) hh[gr * 8 + cg] = pack_h4(a0);
    gr = row0 + rt + 32; if (gr < n) hh[gr * 8 + cg] = pack_h4(a1);
    gr = row0 + rt + 64; if (gr < n) hh[gr * 8 + cg] = pack_h4(a2);
    gr = row0 + rt + 96; if (gr < n) hh[gr * 8 + cg] = pack_h4(a3);
}

// ---------------------------------------------------------------- edge-parallel aggregation
// Thread = (octet of 8 contiguous dst-sorted edges) x (16B column slice c).
// Prefetch all indices + h rows, then register-accumulate, flushing acc*norm_in[d]
// via red.v4 at dst boundaries. LAYER 0: h=g_hh scaled by norm_out[s], into g_agg1.
// LAYER 1: h=g_hh2 (pre-scaled), into outp (pre-initialized to b2).
template <int LAYER>
__global__ __launch_bounds__(256) void edge_agg_kernel(float* __restrict__ outp, int E) {
    int tid = blockIdx.x * blockDim.x + threadIdx.x;
    int oct = tid >> 2;
    int base = oct * 8;
    if (base >= E) return;
    int c = tid & 3;
    float* tgt = (LAYER == 0) ? g_agg1 : outp;
    const uint4* hsrc = (LAYER == 0) ? g_hh : g_hh2;

    int2 e[8];
    if (base + 8 <= E) {
        const int4* p = (const int4*)&g_csr2[base];
        int4 q0 = __ldg(&p[0]);
        int4 q1 = __ldg(&p[1]);
        int4 q2 = __ldg(&p[2]);
        int4 q3 = __ldg(&p[3]);
        e[0] = make_int2(q0.x, q0.y); e[1] = make_int2(q0.z, q0.w);
        e[2] = make_int2(q1.x, q1.y); e[3] = make_int2(q1.z, q1.w);
        e[4] = make_int2(q2.x, q2.y); e[5] = make_int2(q2.z, q2.w);
        e[6] = make_int2(q3.x, q3.y); e[7] = make_int2(q3.z, q3.w);
    } else {
        #pragma unroll
        for (int k = 0; k < 8; k++)
            e[k] = (base + k < E) ? g_csr2[base + k] : make_int2(0, -1);
    }

    // Prefetch all h rows (and src norms for layer 0) — 8-deep MLP.
    uint4 u[8];
    float w[8];
    #pragma unroll
    for (int k = 0; k < 8; k++) {
        int s = e[k].x;
        u[k] = hsrc[s * 4 + c];
        if (LAYER == 0) w[k] = __ldg(&g_norm_out[s]);
        else            w[k] = 1.f;
    }

    // Segmented accumulate + flush.
    float acc[8] = {0.f, 0.f, 0.f, 0.f, 0.f, 0.f, 0.f, 0.f};
    int cur = e[0].y;
    #pragma unroll
    for (int k = 0; k < 8; k++) {
        if (e[k].y < 0) continue;                 // tail padding
        if (e[k].y != cur) {
            flush8(&tgt[cur * 32 + c * 8], acc, __ldg(&g_norm_in[cur]));
            #pragma unroll
            for (int z = 0; z < 8; z++) acc[z] = 0.f;
            cur = e[k].y;
        }
        acc_h8(acc, u[k], w[k]);
    }
    flush8(&tgt[cur * 32 + c * 8], acc, __ldg(&g_norm_in[cur]));
}

// ---------------------------------------------------------------- mid GEMM
// t = relu(agg1 + b1) (agg1 already * norm_in); g_hh2 = (t @ W2) * norm_out (fp16)
__global__ __launch_bounds__(256) void mid_kernel(const float* __restrict__ b1,
                                                  const float* __restrict__ W2, int n) {
    __shared__ float4 sW2[32 * 8];
    __shared__ float4 sT[128 * 8];
    int t = threadIdx.x;
    sW2[t] = ((const float4*)W2)[t];
    int row0 = blockIdx.x * 128;
    #pragma unroll
    for (int j = 0; j < 4; j++) {
        int i = t + j * 256;
        int r = i >> 3, k4 = i & 7;
        int gr = row0 + r;
        float4 v = make_float4(0.f, 0.f, 0.f, 0.f);
        if (gr < n) {
            float4 a = ((const float4*)g_agg1)[gr * 8 + k4];
            float4 b = __ldg(&((const float4*)b1)[k4]);
            v.x = fmaxf(a.x + b.x, 0.f);
            v.y = fmaxf(a.y + b.y, 0.f);
            v.z = fmaxf(a.z + b.z, 0.f);
            v.w = fmaxf(a.w + b.w, 0.f);
        }
        sT[r * 8 + (k4 ^ (r & 7))] = v;
    }
    __syncthreads();

    int rt = t >> 3, cg = t & 7;
    int sw = rt & 7;
    const float4* fp0 = &sT[(rt +  0) * 8];
    const float4* fp1 = &sT[(rt + 32) * 8];
    const float4* fp2 = &sT[(rt + 64) * 8];
    const float4* fp3 = &sT[(rt + 96) * 8];

    float4 a0 = make_float4(0.f,0.f,0.f,0.f), a1 = a0, a2 = a0, a3 = a0;

    #pragma unroll
    for (int k4 = 0; k4 < 8; k4++) {
        float4 f0 = fp0[k4 ^ sw];
        float4 f1 = fp1[k4 ^ sw];
        float4 f2 = fp2[k4 ^ sw];
        float4 f3 = fp3[k4 ^ sw];
        #pragma unroll
        for (int i = 0; i < 4; i++) {
            float4 w = sW2[(k4 * 4 + i) * 8 + cg];
            float c0 = (i == 0) ? f0.x : (i == 1) ? f0.y : (i == 2) ? f0.z : f0.w;
            float c1 = (i == 0) ? f1.x : (i == 1) ? f1.y : (i == 2) ? f1.z : f1.w;
            float c2 = (i == 0) ? f2.x : (i == 1) ? f2.y : (i == 2) ? f2.z : f2.w;
            float c3 = (i == 0) ? f3.x : (i == 1) ? f3.y : (i == 2) ? f3.z : f3.w;
            a0.x += c0*w.x; a0.y += c0*w.y; a0.z += c0*w.z; a0.w += c0*w.w;
            a1.x += c1*w.x; a1.y += c1*w.y; a1.z += c1*w.z; a1.w += c1*w.w;
            a2.x += c2*w.x; a2.y += c2*w.y; a2.z += c2*w.z; a2.w += c2*w.w;
            a3.x += c3*w.x; a3.y += c3*w.y; a3.z += c3*w.z; a3.w += c3*w.w;
        }
    }

    uint2* hh2 = (uint2*)g_hh2;
    #pragma unroll
    for (int j = 0; j < 4; j++) {
        int gr = row0 + rt + 32 * j;
        if (gr < n) {
            float ns = g_norm_out[gr];
            float4 a = (j == 0) ? a0 : (j == 1) ? a1 : (j == 2) ? a2 : a3;
            a.x *= ns; a.y *= ns; a.z *= ns; a.w *= ns;
            hh2[gr * 8 + cg] = pack_h4(a);
        }
    }
}

// ---------------------------------------------------------------- launch
namespace {
struct Ctx {
    cudaStream_t side;
    cudaEvent_t eFork, eJoin;
    Ctx() {
        cudaStreamCreateWithFlags(&side, cudaStreamNonBlocking);
        cudaEventCreateWithFlags(&eFork, cudaEventDisableTiming);
        cudaEventCreateWithFlags(&eJoin, cudaEventDisableTiming);
        cudaFuncSetAttribute(gemm1_kernel,
                             cudaFuncAttributeMaxDynamicSharedMemorySize, 81920);
    }
};
}

extern "C" void kernel_launch(void* const* d_in, const int* in_sizes, int n_in,
                              void* d_out, int out_size) {
    static Ctx ctx;   // resource init only (streams/events/attr), no cached work

    const float* feat = (const float*)d_in[0];
    const float* W1   = (const float*)d_in[1];
    const float* b1   = (const float*)d_in[2];
    const float* W2   = (const float*)d_in[3];
    const float* b2   = (const float*)d_in[4];
    const int*   src  = (const int*)d_in[5];
    const int*   dst  = (const int*)d_in[6];
    float* out = (float*)d_out;

    int n = in_sizes[0] / 128;
    int E = in_sizes[5];

    const int B = 256;
    int gblocks = (n + 127) / 128;
    int nb = (n + SCAN_B - 1) / SCAN_B;
    int dthreads = (E + 3) / 4;
    int octs = (E + 7) / 8;
    int eblocks = (octs * 4 + B - 1) / B;

    // Fork: gemm1 (independent of graph structure) on side stream.
    cudaEventRecord(ctx.eFork, 0);
    cudaStreamWaitEvent(ctx.side, ctx.eFork, 0);
    gemm1_kernel<<<gblocks, 256, 81920, ctx.side>>>(feat, W1, n);
    cudaEventRecord(ctx.eJoin, ctx.side);

    // Main stream: zero/out-init -> degrees -> scan(+norms) -> scatter (under gemm1).
    zero_kernel      <<<(n * 8 + B - 1) / B, B>>>((float4*)out, b2, n);
    degree_kernel    <<<(dthreads + B - 1) / B, B>>>(src, dst, E);
    scanA_norm_kernel<<<nb, SCAN_B>>>(n);
    scanB_kernel     <<<1, 256>>>(nb);
    scatter_kernel   <<<(E + B - 1) / B, B>>>(src, dst, E);

    // Join: edge_agg1 needs g_hh (gemm1) + csr2/norms (main chain).
    cudaStreamWaitEvent(0, ctx.eJoin, 0);

    edge_agg_kernel<0><<<eblocks, B>>>(out, E);
    mid_kernel        <<<gblocks, 256>>>(b1, W2, n);
    edge_agg_kernel<1><<<eblocks, B>>>(out, E);
}